// round 11
// baseline (speedup 1.0000x reference)
#include <cuda_runtime.h>
#include <cuda_pipeline.h>
#include <cuda_fp16.h>
#include <math.h>
#include <stdint.h>

#define SEQ  4097
#define SEQP 4224          // 33 * 128, padded
#define H    1024
#define NH   16
#define HD   64
#define H3   3072
#define FFD  4096
#define LAYERS 6
#define OUTD 128

#define WQKV_N (LAYERS * H3 * H)
#define WO_N   (LAYERS * H * H)
#define W1_N   (LAYERS * FFD * H)
#define W2_N   (LAYERS * H * FFD)

// ---------------- scratch (device globals; no allocations) ----------------
__device__ float  g_x[SEQP * H];
__device__ __half g_xh[SEQP * H];
__device__ __half g_qkv[SEQP * H3];
__device__ __half g_attn[SEQP * H];
__device__ float  g_tmp[SEQP * H];
__device__ __half g_ff[SEQP * FFD];
__device__ __half g_wqkv_h[WQKV_N];
__device__ __half g_wo_h[WO_N];
__device__ __half g_w1_h[W1_N];
__device__ __half g_w2_h[W2_N];

__device__ __forceinline__ void mma_f16(float& d0, float& d1, float& d2, float& d3,
                                        uint32_t a0, uint32_t a1, uint32_t a2, uint32_t a3,
                                        uint32_t b0, uint32_t b1)
{
    asm volatile("mma.sync.aligned.m16n8k16.row.col.f32.f16.f16.f32 "
                 "{%0,%1,%2,%3},{%4,%5,%6,%7},{%8,%9},{%0,%1,%2,%3};"
                 : "+f"(d0), "+f"(d1), "+f"(d2), "+f"(d3)
                 : "r"(a0), "r"(a1), "r"(a2), "r"(a3), "r"(b0), "r"(b1));
}

__device__ __forceinline__ void ldsm4(uint32_t& r0, uint32_t& r1, uint32_t& r2, uint32_t& r3,
                                      uint32_t addr)
{
    asm volatile("ldmatrix.sync.aligned.m8n8.x4.shared.b16 {%0,%1,%2,%3}, [%4];"
                 : "=r"(r0), "=r"(r1), "=r"(r2), "=r"(r3) : "r"(addr));
}

__device__ __forceinline__ void ldsm4t(uint32_t& r0, uint32_t& r1, uint32_t& r2, uint32_t& r3,
                                       uint32_t addr)
{
    asm volatile("ldmatrix.sync.aligned.m8n8.x4.trans.shared.b16 {%0,%1,%2,%3}, [%4];"
                 : "=r"(r0), "=r"(r1), "=r"(r2), "=r"(r3) : "r"(addr));
}

__device__ __forceinline__ uint32_t pack_h2(float a, float b) {
    __half2 h = __floats2half2_rn(a, b);
    return *(uint32_t*)&h;
}

__device__ __forceinline__ float ex2f(float x) {
    float y;
    asm("ex2.approx.ftz.f32 %0, %1;" : "=f"(y) : "f"(x));
    return y;
}

// ---------------- fp16 conversion: all four weight tensors, one launch ----------------
__global__ void to_half_all_kernel(const float* __restrict__ w0, __half* __restrict__ o0,
                                   const float* __restrict__ w1, __half* __restrict__ o1,
                                   const float* __restrict__ w2, __half* __restrict__ o2,
                                   const float* __restrict__ w3, __half* __restrict__ o3)
{
    const int n0 = WQKV_N / 4, n1 = WO_N / 4, n2 = W1_N / 4, n3 = W2_N / 4;
    const int total = n0 + n1 + n2 + n3;
    for (int i = blockIdx.x * blockDim.x + threadIdx.x; i < total; i += gridDim.x * blockDim.x) {
        const float* in; __half* out; int j = i;
        if (j < n0)                { in = w0; out = o0; }
        else if ((j -= n0) < n1)   { in = w1; out = o1; }
        else if ((j -= n1) < n2)   { in = w2; out = o2; }
        else { j -= n2;              in = w3; out = o3; }
        float4 v = ((const float4*)in)[j];
        ((__half2*)out)[2 * j]     = __floats2half2_rn(v.x, v.y);
        ((__half2*)out)[2 * j + 1] = __floats2half2_rn(v.z, v.w);
    }
}

// ---------------- embedding (writes x and fp16 xh) ----------------
__global__ void embed_kernel(
    const float* __restrict__ q, const float* __restrict__ p,
    const float* __restrict__ qm, const float* __restrict__ pm,
    const float* __restrict__ z,
    const float* __restrict__ Wq, const float* __restrict__ bq,
    const float* __restrict__ Wp, const float* __restrict__ bp,
    const float* __restrict__ Wz, const float* __restrict__ bz,
    const float* __restrict__ pos, const float* __restrict__ noise,
    float* __restrict__ x, __half* __restrict__ xh)
{
    int s = blockIdx.x;
    if (s >= SEQ) {
        for (int h = threadIdx.x; h < H; h += blockDim.x) {
            x[(size_t)s * H + h] = 0.0f;
            xh[(size_t)s * H + h] = __float2half(0.0f);
        }
        return;
    }
    __shared__ float vin[128];
    const float *W, *b, *src;
    int dim;
    float mask;
    if (s == 0)          { src = z;                   dim = 128; W = Wz; b = bz; mask = 1.0f; }
    else if (s <= 2048)  { src = q + (s - 1) * 64;    dim = 64;  W = Wq; b = bq; mask = qm[s - 1]; }
    else                 { src = p + (s - 2049) * 64; dim = 64;  W = Wp; b = bp; mask = pm[s - 2049]; }

    for (int i = threadIdx.x; i < dim; i += blockDim.x) vin[i] = src[i];
    __syncthreads();

    int idx = (int)(mask * 100.0f);
    const float* ne = noise + (size_t)idx * H;

    for (int h = threadIdx.x; h < H; h += blockDim.x) {
        const float* w = W + (size_t)h * dim;
        float acc = b[h];
#pragma unroll 8
        for (int d = 0; d < dim; d++) acc = fmaf(vin[d], w[d], acc);
        float v = acc + pos[(size_t)s * H + h] + ne[h];
        x[(size_t)s * H + h] = v;
        xh[(size_t)s * H + h] = __float2half_rn(v);
    }
}

// ---------------- fp16 GEMM: block 128x64, warp tile 32x32, 3 blocks/SM ----------------
#define AST 72
#define ATILE_H (128 * AST)            // A tile halves
#define BTILE_H (64 * AST)             // B tile halves
#define GEMM_SMEM ((2 * ATILE_H + 2 * BTILE_H) * 2)   // 55296 B

template <bool RELU, bool HOUT>
__global__ __launch_bounds__(256, 3)
void tgemm(const __half* __restrict__ A, const __half* __restrict__ W,
           const float* __restrict__ bias, void* __restrict__ Cv,
           int M, int N, int K)
{
    extern __shared__ __half smg[];
    __half* AsBuf[2] = { smg,                           smg + ATILE_H + BTILE_H };
    __half* BsBuf[2] = { smg + ATILE_H,                 smg + 2 * ATILE_H + BTILE_H };

    const int t    = threadIdx.x;
    const int lane = t & 31;
    const int w    = t >> 5;
    const int bm = blockIdx.y * 128, bn = blockIdx.x * 64;
    const int wm = w >> 1, wn = w & 1;          // wm 0..3 (32 rows), wn 0..1 (32 cols)
    const int quad = lane >> 2, tig = lane & 3;

    const int a_row  = (lane & 7) + ((lane >> 3) & 1) * 8;
    const int a_koff = ((lane >> 4) & 1) * 8;
    const int b_row  = (lane & 7) + ((lane & 16) >> 1);
    const int b_koff = ((lane >> 3) & 1) * 8;

    const __half* Ab = A + (size_t)bm * K;
    const __half* Wb = W + (size_t)bn * K;

    float c[2][4][4];
#pragma unroll
    for (int mi = 0; mi < 2; mi++)
#pragma unroll
        for (int ni = 0; ni < 4; ni++)
#pragma unroll
            for (int e = 0; e < 4; e++) c[mi][ni][e] = 0.f;

    const int kt = K / 64;

    auto stage = [&](int buf, int k0) {
#pragma unroll
        for (int v = 0; v < 4; v++) {              // A: 1024 chunks / 256 thr
            int linear = t + v * 256;
            int row = linear >> 3;
            int off = (linear & 7) * 8;
            __pipeline_memcpy_async(&AsBuf[buf][row * AST + off],
                                    Ab + (size_t)row * K + k0 + off, 16);
        }
#pragma unroll
        for (int v = 0; v < 2; v++) {              // B: 512 chunks / 256 thr
            int linear = t + v * 256;
            int row = linear >> 3;
            int off = (linear & 7) * 8;
            __pipeline_memcpy_async(&BsBuf[buf][row * AST + off],
                                    Wb + (size_t)row * K + k0 + off, 16);
        }
        __pipeline_commit();
    };

    stage(0, 0);
    for (int it = 0; it < kt; it++) {
        __pipeline_wait_prior(0);
        __syncthreads();
        if (it + 1 < kt) stage((it + 1) & 1, (it + 1) * 64);

        const __half* Ap = AsBuf[it & 1];
        const __half* Bp = BsBuf[it & 1];
        uint32_t aBase = (uint32_t)__cvta_generic_to_shared(
            Ap + (wm * 32 + a_row) * AST + a_koff);
        uint32_t bBase = (uint32_t)__cvta_generic_to_shared(
            Bp + (wn * 32 + b_row) * AST + b_koff);

#pragma unroll
        for (int kk = 0; kk < 64; kk += 16) {
            uint32_t a[2][4];
#pragma unroll
            for (int mi = 0; mi < 2; mi++)
                ldsm4(a[mi][0], a[mi][1], a[mi][2], a[mi][3],
                      aBase + (uint32_t)((mi * 16 * AST + kk) * 2));
            uint32_t bf[8];
            ldsm4(bf[0], bf[1], bf[2], bf[3], bBase + (uint32_t)(kk * 2));
            ldsm4(bf[4], bf[5], bf[6], bf[7], bBase + (uint32_t)((16 * AST + kk) * 2));
#pragma unroll
            for (int mi = 0; mi < 2; mi++)
#pragma unroll
                for (int ni = 0; ni < 4; ni++)
                    mma_f16(c[mi][ni][0], c[mi][ni][1], c[mi][ni][2], c[mi][ni][3],
                            a[mi][0], a[mi][1], a[mi][2], a[mi][3],
                            bf[2 * ni], bf[2 * ni + 1]);
        }
    }

#pragma unroll
    for (int mi = 0; mi < 2; mi++) {
        int row0 = bm + wm * 32 + mi * 16 + quad;
#pragma unroll
        for (int ni = 0; ni < 4; ni++) {
            int col = bn + wn * 32 + ni * 8 + tig * 2;
            float2 bb = *(const float2*)&bias[col];
            float v00 = c[mi][ni][0] + bb.x, v01 = c[mi][ni][1] + bb.y;
            float v10 = c[mi][ni][2] + bb.x, v11 = c[mi][ni][3] + bb.y;
            if (RELU) {
                v00 = fmaxf(v00, 0.f); v01 = fmaxf(v01, 0.f);
                v10 = fmaxf(v10, 0.f); v11 = fmaxf(v11, 0.f);
            }
            if (HOUT) {
                __half* C = (__half*)Cv;
                *(__half2*)&C[(size_t)row0 * N + col]       = __floats2half2_rn(v00, v01);
                *(__half2*)&C[(size_t)(row0 + 8) * N + col] = __floats2half2_rn(v10, v11);
            } else {
                float* C = (float*)Cv;
                *(float2*)&C[(size_t)row0 * N + col]       = make_float2(v00, v01);
                *(float2*)&C[(size_t)(row0 + 8) * N + col] = make_float2(v10, v11);
            }
        }
    }
}

// ---------------- flash attention: fp16 mma, P in registers, exp2 softmax ----------------
#define KST 72
#define VST 72
#define KBUF (64 * KST)
#define VBUF (64 * VST)
#define ATTN_SMEM ((2 * KBUF + 2 * VBUF) * 2)   // 36864 B
#define QSCALE (0.125f * 1.44269504088896f)     // 1/sqrt(64) * log2(e)

__global__ __launch_bounds__(256, 2)
void attn_kernel(const __half* __restrict__ qkv, __half* __restrict__ out)
{
    extern __shared__ __half sma[];
    __half* Ksm[2] = { sma, sma + KBUF };
    __half* Vsm[2] = { sma + 2 * KBUF, sma + 2 * KBUF + VBUF };

    const int t    = threadIdx.x;
    const int lane = t & 31;
    const int w    = t >> 5;
    const int quad = lane >> 2;
    const int tig  = lane & 3;
    const int head = blockIdx.y;
    const int q0   = blockIdx.x * 128;
    const int coff = head * 64;

    const int b_row  = (lane & 7) + ((lane & 16) >> 1);
    const int b_koff = ((lane >> 3) & 1) * 8;
    const int v_row  = (lane & 7) + ((lane >> 3) & 1) * 8;
    const int v_coff = ((lane >> 4) & 1) * 8;

    auto stage = [&](int k0, int buf) {
#pragma unroll
        for (int v = 0; v < 2; v++) {
            int linear = t + v * 256;
            int row = linear >> 3;
            int off = (linear & 7) * 8;
            __pipeline_memcpy_async(&Ksm[buf][row * KST + off],
                                    &qkv[(size_t)(k0 + row) * H3 + H + coff + off], 16);
            __pipeline_memcpy_async(&Vsm[buf][row * VST + off],
                                    &qkv[(size_t)(k0 + row) * H3 + 2 * H + coff + off], 16);
        }
        __pipeline_commit();
    };

    uint32_t Qa[4][4];
    {
        const __half* qb = qkv + (size_t)(q0 + w * 16) * H3 + coff;
#pragma unroll
        for (int c = 0; c < 4; c++) {
#pragma unroll
            for (int e = 0; e < 4; e++) {
                int r   = quad + (e & 1) * 8;
                int col = c * 16 + (e >> 1) * 8 + tig * 2;
                float2 v = __half22float2(*(const __half2*)&qb[(size_t)r * H3 + col]);
                Qa[c][e] = pack_h2(v.x * QSCALE, v.y * QSCALE);
            }
        }
    }

    float o[8][4];
#pragma unroll
    for (int nb = 0; nb < 8; nb++)
#pragma unroll
        for (int e = 0; e < 4; e++) o[nb][e] = 0.f;
    float m0 = -1e30f, m1 = -1e30f, l0 = 0.f, l1 = 0.f;

    const int NITER = (SEQ + 63) / 64;   // 65

    stage(0, 0);
    for (int it = 0; it < NITER; it++) {
        const int k0 = it * 64;
        __pipeline_wait_prior(0);
        __syncthreads();
        if (it + 1 < NITER) stage((it + 1) * 64, (it + 1) & 1);

        const __half* Kb = Ksm[it & 1];
        const __half* Vb = Vsm[it & 1];

        uint32_t kBase = (uint32_t)__cvta_generic_to_shared(Kb + b_row * KST + b_koff);
        uint32_t vBase = (uint32_t)__cvta_generic_to_shared(Vb + v_row * VST + v_coff);

        // ---- S = Q @ K^T (scores already in log2 domain via QSCALE) ----
        float s[8][4];
#pragma unroll
        for (int nb = 0; nb < 8; nb++)
            s[nb][0] = s[nb][1] = s[nb][2] = s[nb][3] = 0.f;
#pragma unroll
        for (int jn = 0; jn < 4; jn++) {
#pragma unroll
            for (int c = 0; c < 4; c++) {
                uint32_t bf[4];
                ldsm4(bf[0], bf[1], bf[2], bf[3],
                      kBase + (uint32_t)((jn * 16 * KST + c * 16) * 2));
                mma_f16(s[2*jn][0], s[2*jn][1], s[2*jn][2], s[2*jn][3],
                        Qa[c][0], Qa[c][1], Qa[c][2], Qa[c][3], bf[0], bf[1]);
                mma_f16(s[2*jn+1][0], s[2*jn+1][1], s[2*jn+1][2], s[2*jn+1][3],
                        Qa[c][0], Qa[c][1], Qa[c][2], Qa[c][3], bf[2], bf[3]);
            }
        }

        if (k0 + 64 > SEQ) {
#pragma unroll
            for (int jb = 0; jb < 8; jb++) {
                int col0 = k0 + jb * 8 + 2 * tig;
                if (col0 >= SEQ)     { s[jb][0] = -1e30f; s[jb][2] = -1e30f; }
                if (col0 + 1 >= SEQ) { s[jb][1] = -1e30f; s[jb][3] = -1e30f; }
            }
        }

        // ---- online softmax in log2 domain (p = 2^(s - mn)) ----
        float mx0 = -1e30f, mx1 = -1e30f;
#pragma unroll
        for (int jb = 0; jb < 8; jb++) {
            mx0 = fmaxf(mx0, fmaxf(s[jb][0], s[jb][1]));
            mx1 = fmaxf(mx1, fmaxf(s[jb][2], s[jb][3]));
        }
        mx0 = fmaxf(mx0, __shfl_xor_sync(0xffffffffu, mx0, 1));
        mx0 = fmaxf(mx0, __shfl_xor_sync(0xffffffffu, mx0, 2));
        mx1 = fmaxf(mx1, __shfl_xor_sync(0xffffffffu, mx1, 1));
        mx1 = fmaxf(mx1, __shfl_xor_sync(0xffffffffu, mx1, 2));

        float mn0 = fmaxf(m0, mx0), mn1 = fmaxf(m1, mx1);
        float corr0 = ex2f(m0 - mn0), corr1 = ex2f(m1 - mn1);
        m0 = mn0; m1 = mn1;

        float sum0 = 0.f, sum1 = 0.f;
#pragma unroll
        for (int jb = 0; jb < 8; jb++) {
            float p0 = ex2f(s[jb][0] - mn0);
            float p1 = ex2f(s[jb][1] - mn0);
            float p2 = ex2f(s[jb][2] - mn1);
            float p3 = ex2f(s[jb][3] - mn1);
            sum0 += p0 + p1;
            sum1 += p2 + p3;
            s[jb][0] = p0; s[jb][1] = p1; s[jb][2] = p2; s[jb][3] = p3;
        }
        sum0 += __shfl_xor_sync(0xffffffffu, sum0, 1);
        sum0 += __shfl_xor_sync(0xffffffffu, sum0, 2);
        sum1 += __shfl_xor_sync(0xffffffffu, sum1, 1);
        sum1 += __shfl_xor_sync(0xffffffffu, sum1, 2);
        l0 = l0 * corr0 + sum0;
        l1 = l1 * corr1 + sum1;

#pragma unroll
        for (int nb = 0; nb < 8; nb++) {
            o[nb][0] *= corr0; o[nb][1] *= corr0;
            o[nb][2] *= corr1; o[nb][3] *= corr1;
        }

        // ---- O += P @ V (P packed straight from S accumulators) ----
#pragma unroll
        for (int kc = 0; kc < 4; kc++) {
            uint32_t pf0 = pack_h2(s[2*kc][0],   s[2*kc][1]);
            uint32_t pf1 = pack_h2(s[2*kc][2],   s[2*kc][3]);
            uint32_t pf2 = pack_h2(s[2*kc+1][0], s[2*kc+1][1]);
            uint32_t pf3 = pack_h2(s[2*kc+1][2], s[2*kc+1][3]);
#pragma unroll
            for (int jn = 0; jn < 4; jn++) {
                uint32_t bf[4];
                ldsm4t(bf[0], bf[1], bf[2], bf[3],
                       vBase + (uint32_t)((kc * 16 * VST + jn * 16) * 2));
                mma_f16(o[2*jn][0], o[2*jn][1], o[2*jn][2], o[2*jn][3],
                        pf0, pf1, pf2, pf3, bf[0], bf[1]);
                mma_f16(o[2*jn+1][0], o[2*jn+1][1], o[2*jn+1][2], o[2*jn+1][3],
                        pf0, pf1, pf2, pf3, bf[2], bf[3]);
            }
        }
    }

    float inv0 = 1.0f / l0, inv1 = 1.0f / l1;
    __half* ob0 = out + (size_t)(q0 + w * 16 + quad) * H + coff;
    __half* ob1 = out + (size_t)(q0 + w * 16 + quad + 8) * H + coff;
#pragma unroll
    for (int nb = 0; nb < 8; nb++) {
        *(__half2*)&ob0[nb * 8 + 2 * tig] = __floats2half2_rn(o[nb][0] * inv0, o[nb][1] * inv0);
        *(__half2*)&ob1[nb * 8 + 2 * tig] = __floats2half2_rn(o[nb][2] * inv1, o[nb][3] * inv1);
    }
}

// ---------------- fused add + LayerNorm (writes x and fp16 xh) ----------------
__global__ __launch_bounds__(256)
void addln_kernel(const float* __restrict__ a, const float* __restrict__ b,
                  const float* __restrict__ w, const float* __restrict__ wb,
                  float* __restrict__ outx, __half* __restrict__ outxh)
{
    int s = blockIdx.x;
    int t = threadIdx.x;
    const float4 av = ((const float4*)(a + (size_t)s * H))[t];
    const float4 bv = ((const float4*)(b + (size_t)s * H))[t];
    float v[4] = {av.x + bv.x, av.y + bv.y, av.z + bv.z, av.w + bv.w};

    float s1 = v[0] + v[1] + v[2] + v[3];
    float s2 = v[0]*v[0] + v[1]*v[1] + v[2]*v[2] + v[3]*v[3];
#pragma unroll
    for (int off = 16; off > 0; off >>= 1) {
        s1 += __shfl_xor_sync(0xffffffffu, s1, off);
        s2 += __shfl_xor_sync(0xffffffffu, s2, off);
    }
    __shared__ float r1[8], r2[8];
    int wid = t >> 5, lane = t & 31;
    if (lane == 0) { r1[wid] = s1; r2[wid] = s2; }
    __syncthreads();
    if (t == 0) {
        float a0 = 0.f, b0 = 0.f;
#pragma unroll
        for (int i = 0; i < 8; i++) { a0 += r1[i]; b0 += r2[i]; }
        r1[0] = a0; r2[0] = b0;
    }
    __syncthreads();
    float mean = r1[0] * (1.0f / H);
    float var  = r2[0] * (1.0f / H) - mean * mean;
    float rstd = rsqrtf(var + 1e-5f);

    const float4 wv  = ((const float4*)w)[t];
    const float4 wbv = ((const float4*)wb)[t];
    float4 ov;
    ov.x = (v[0] - mean) * rstd * wv.x + wbv.x;
    ov.y = (v[1] - mean) * rstd * wv.y + wbv.y;
    ov.z = (v[2] - mean) * rstd * wv.z + wbv.z;
    ov.w = (v[3] - mean) * rstd * wv.w + wbv.w;
    ((float4*)(outx + (size_t)s * H))[t] = ov;

    ((__half2*)(outxh + (size_t)s * H))[2 * t]     = __floats2half2_rn(ov.x, ov.y);
    ((__half2*)(outxh + (size_t)s * H))[2 * t + 1] = __floats2half2_rn(ov.z, ov.w);
}

// ---------------- final projection ----------------
__global__ void final_kernel(const float* __restrict__ x, const float* __restrict__ Wout,
                             const float* __restrict__ bout, float* __restrict__ out)
{
    int o = threadIdx.x;
    if (o >= OUTD) return;
    const float* w = Wout + (size_t)o * H;
    float acc = bout[o];
#pragma unroll 8
    for (int d = 0; d < H; d++) acc = fmaf(x[d], w[d], acc);
    out[o] = acc;
}

// ---------------- launch ----------------
extern "C" void kernel_launch(void* const* d_in, const int* in_sizes, int n_in,
                              void* d_out, int out_size)
{
    (void)in_sizes; (void)n_in; (void)out_size;
    const float* q     = (const float*)d_in[0];
    const float* p     = (const float*)d_in[1];
    const float* qm    = (const float*)d_in[2];
    const float* pm    = (const float*)d_in[3];
    const float* z     = (const float*)d_in[4];
    const float* Wq    = (const float*)d_in[5];
    const float* bq    = (const float*)d_in[6];
    const float* Wp    = (const float*)d_in[7];
    const float* bp    = (const float*)d_in[8];
    const float* Wz    = (const float*)d_in[9];
    const float* bz    = (const float*)d_in[10];
    const float* pos   = (const float*)d_in[11];
    const float* noise = (const float*)d_in[12];
    const float* Wqkv  = (const float*)d_in[13];
    const float* bqkv  = (const float*)d_in[14];
    const float* Wo    = (const float*)d_in[15];
    const float* bo    = (const float*)d_in[16];
    const float* ln1w  = (const float*)d_in[17];
    const float* ln1b  = (const float*)d_in[18];
    const float* W1    = (const float*)d_in[19];
    const float* b1    = (const float*)d_in[20];
    const float* W2    = (const float*)d_in[21];
    const float* b2    = (const float*)d_in[22];
    const float* ln2w  = (const float*)d_in[23];
    const float* ln2b  = (const float*)d_in[24];
    const float* Wout  = (const float*)d_in[25];
    const float* bout  = (const float*)d_in[26];

    float *x, *tmp;
    __half *xh, *qkvb, *attnb, *ff, *wqkv_h, *wo_h, *w1_h, *w2_h;
    cudaGetSymbolAddress((void**)&x,      g_x);
    cudaGetSymbolAddress((void**)&xh,     g_xh);
    cudaGetSymbolAddress((void**)&qkvb,   g_qkv);
    cudaGetSymbolAddress((void**)&attnb,  g_attn);
    cudaGetSymbolAddress((void**)&tmp,    g_tmp);
    cudaGetSymbolAddress((void**)&ff,     g_ff);
    cudaGetSymbolAddress((void**)&wqkv_h, g_wqkv_h);
    cudaGetSymbolAddress((void**)&wo_h,   g_wo_h);
    cudaGetSymbolAddress((void**)&w1_h,   g_w1_h);
    cudaGetSymbolAddress((void**)&w2_h,   g_w2_h);

    cudaFuncSetAttribute((const void*)tgemm<false,true>,  cudaFuncAttributeMaxDynamicSharedMemorySize, GEMM_SMEM);
    cudaFuncSetAttribute((const void*)tgemm<false,false>, cudaFuncAttributeMaxDynamicSharedMemorySize, GEMM_SMEM);
    cudaFuncSetAttribute((const void*)tgemm<true,true>,   cudaFuncAttributeMaxDynamicSharedMemorySize, GEMM_SMEM);
    cudaFuncSetAttribute((const void*)attn_kernel,        cudaFuncAttributeMaxDynamicSharedMemorySize, ATTN_SMEM);

    to_half_all_kernel<<<4096, 256>>>(Wqkv, wqkv_h, Wo, wo_h, W1, w1_h, W2, w2_h);

    embed_kernel<<<SEQP, 256>>>(q, p, qm, pm, z, Wq, bq, Wp, bp, Wz, bz, pos, noise, x, xh);

    const int MB = SEQP / 128;   // 33
    for (int i = 0; i < LAYERS; i++) {
        tgemm<false,true><<<dim3(H3 / 64, MB), 256, GEMM_SMEM>>>(
            xh, wqkv_h + (size_t)i * H3 * H, bqkv + (size_t)i * H3, qkvb, SEQP, H3, H);
        attn_kernel<<<dim3(SEQP / 128, NH), 256, ATTN_SMEM>>>(qkvb, attnb);
        tgemm<false,false><<<dim3(H / 64, MB), 256, GEMM_SMEM>>>(
            attnb, wo_h + (size_t)i * H * H, bo + (size_t)i * H, tmp, SEQP, H, H);
        addln_kernel<<<SEQP, 256>>>(x, tmp, ln1w + (size_t)i * H, ln1b + (size_t)i * H, x, xh);
        tgemm<true,true><<<dim3(FFD / 64, MB), 256, GEMM_SMEM>>>(
            xh, w1_h + (size_t)i * FFD * H, b1 + (size_t)i * FFD, ff, SEQP, FFD, H);
        tgemm<false,false><<<dim3(H / 64, MB), 256, GEMM_SMEM>>>(
            ff, w2_h + (size_t)i * H * FFD, b2 + (size_t)i * H, tmp, SEQP, H, FFD);
        addln_kernel<<<SEQP, 256>>>(x, tmp, ln2w + (size_t)i * H, ln2b + (size_t)i * H, x, xh);
    }

    final_kernel<<<1, 128>>>(x, Wout, bout, (float*)d_out);
}

// round 12
// speedup vs baseline: 1.0394x; 1.0394x over previous
#include <cuda_runtime.h>
#include <cuda_pipeline.h>
#include <cuda_fp16.h>
#include <math.h>
#include <stdint.h>

#define SEQ  4097
#define SEQP 4224          // 33 * 128, padded
#define H    1024
#define NH   16
#define HD   64
#define H3   3072
#define FFD  4096
#define LAYERS 6
#define OUTD 128

#define WQKV_N (LAYERS * H3 * H)
#define WO_N   (LAYERS * H * H)
#define W1_N   (LAYERS * FFD * H)
#define W2_N   (LAYERS * H * FFD)

// ---------------- scratch (device globals; no allocations) ----------------
__device__ float  g_x[SEQP * H];
__device__ __half g_xh[SEQP * H];
__device__ __half g_qkv[SEQP * H3];
__device__ __half g_attn[SEQP * H];
__device__ float  g_tmp[SEQP * H];
__device__ __half g_ff[SEQP * FFD];
__device__ __half g_wqkv_h[WQKV_N];
__device__ __half g_wo_h[WO_N];
__device__ __half g_w1_h[W1_N];
__device__ __half g_w2_h[W2_N];

__device__ __forceinline__ void mma_f16(float& d0, float& d1, float& d2, float& d3,
                                        uint32_t a0, uint32_t a1, uint32_t a2, uint32_t a3,
                                        uint32_t b0, uint32_t b1)
{
    asm volatile("mma.sync.aligned.m16n8k16.row.col.f32.f16.f16.f32 "
                 "{%0,%1,%2,%3},{%4,%5,%6,%7},{%8,%9},{%0,%1,%2,%3};"
                 : "+f"(d0), "+f"(d1), "+f"(d2), "+f"(d3)
                 : "r"(a0), "r"(a1), "r"(a2), "r"(a3), "r"(b0), "r"(b1));
}

__device__ __forceinline__ void ldsm4(uint32_t& r0, uint32_t& r1, uint32_t& r2, uint32_t& r3,
                                      uint32_t addr)
{
    asm volatile("ldmatrix.sync.aligned.m8n8.x4.shared.b16 {%0,%1,%2,%3}, [%4];"
                 : "=r"(r0), "=r"(r1), "=r"(r2), "=r"(r3) : "r"(addr));
}

__device__ __forceinline__ void ldsm4t(uint32_t& r0, uint32_t& r1, uint32_t& r2, uint32_t& r3,
                                       uint32_t addr)
{
    asm volatile("ldmatrix.sync.aligned.m8n8.x4.trans.shared.b16 {%0,%1,%2,%3}, [%4];"
                 : "=r"(r0), "=r"(r1), "=r"(r2), "=r"(r3) : "r"(addr));
}

__device__ __forceinline__ uint32_t pack_h2(float a, float b) {
    __half2 h = __floats2half2_rn(a, b);
    return *(uint32_t*)&h;
}

__device__ __forceinline__ float ex2f(float x) {
    float y;
    asm("ex2.approx.ftz.f32 %0, %1;" : "=f"(y) : "f"(x));
    return y;
}

// ---------------- fp16 conversion: all four weight tensors, one launch ----------------
__global__ void to_half_all_kernel(const float* __restrict__ w0, __half* __restrict__ o0,
                                   const float* __restrict__ w1, __half* __restrict__ o1,
                                   const float* __restrict__ w2, __half* __restrict__ o2,
                                   const float* __restrict__ w3, __half* __restrict__ o3)
{
    const int n0 = WQKV_N / 4, n1 = WO_N / 4, n2 = W1_N / 4, n3 = W2_N / 4;
    const int total = n0 + n1 + n2 + n3;
    for (int i = blockIdx.x * blockDim.x + threadIdx.x; i < total; i += gridDim.x * blockDim.x) {
        const float* in; __half* out; int j = i;
        if (j < n0)                { in = w0; out = o0; }
        else if ((j -= n0) < n1)   { in = w1; out = o1; }
        else if ((j -= n1) < n2)   { in = w2; out = o2; }
        else { j -= n2;              in = w3; out = o3; }
        float4 v = ((const float4*)in)[j];
        ((__half2*)out)[2 * j]     = __floats2half2_rn(v.x, v.y);
        ((__half2*)out)[2 * j + 1] = __floats2half2_rn(v.z, v.w);
    }
}

// ---------------- embedding (writes x and fp16 xh) ----------------
__global__ void embed_kernel(
    const float* __restrict__ q, const float* __restrict__ p,
    const float* __restrict__ qm, const float* __restrict__ pm,
    const float* __restrict__ z,
    const float* __restrict__ Wq, const float* __restrict__ bq,
    const float* __restrict__ Wp, const float* __restrict__ bp,
    const float* __restrict__ Wz, const float* __restrict__ bz,
    const float* __restrict__ pos, const float* __restrict__ noise,
    float* __restrict__ x, __half* __restrict__ xh)
{
    int s = blockIdx.x;
    if (s >= SEQ) {
        for (int h = threadIdx.x; h < H; h += blockDim.x) {
            x[(size_t)s * H + h] = 0.0f;
            xh[(size_t)s * H + h] = __float2half(0.0f);
        }
        return;
    }
    __shared__ float vin[128];
    const float *W, *b, *src;
    int dim;
    float mask;
    if (s == 0)          { src = z;                   dim = 128; W = Wz; b = bz; mask = 1.0f; }
    else if (s <= 2048)  { src = q + (s - 1) * 64;    dim = 64;  W = Wq; b = bq; mask = qm[s - 1]; }
    else                 { src = p + (s - 2049) * 64; dim = 64;  W = Wp; b = bp; mask = pm[s - 2049]; }

    for (int i = threadIdx.x; i < dim; i += blockDim.x) vin[i] = src[i];
    __syncthreads();

    int idx = (int)(mask * 100.0f);
    const float* ne = noise + (size_t)idx * H;

    for (int h = threadIdx.x; h < H; h += blockDim.x) {
        const float* w = W + (size_t)h * dim;
        float acc = b[h];
#pragma unroll 8
        for (int d = 0; d < dim; d++) acc = fmaf(vin[d], w[d], acc);
        float v = acc + pos[(size_t)s * H + h] + ne[h];
        x[(size_t)s * H + h] = v;
        xh[(size_t)s * H + h] = __float2half_rn(v);
    }
}

// ---------------- fp16 GEMM: R10 config (128x128 block, 64x32 warp tile) ----------------
#define AST 72
#define GTILE (128 * AST)
#define GEMM_SMEM (4 * GTILE * 2)

template <bool RELU, bool HOUT>
__global__ __launch_bounds__(256, 2)
void tgemm(const __half* __restrict__ A, const __half* __restrict__ W,
           const float* __restrict__ bias, void* __restrict__ Cv,
           int M, int N, int K)
{
    extern __shared__ __half smg[];
    __half* AsBuf[2] = { smg,         smg + 2 * GTILE };
    __half* BsBuf[2] = { smg + GTILE, smg + 3 * GTILE };

    const int t    = threadIdx.x;
    const int lane = t & 31;
    const int w    = t >> 5;
    const int bm = blockIdx.y * 128, bn = blockIdx.x * 128;
    const int wm = w >> 2, wn = w & 3;
    const int quad = lane >> 2, tig = lane & 3;

    const int a_row  = (lane & 7) + ((lane >> 3) & 1) * 8;
    const int a_koff = ((lane >> 4) & 1) * 8;
    const int b_row  = (lane & 7) + ((lane & 16) >> 1);
    const int b_koff = ((lane >> 3) & 1) * 8;

    const __half* Ab = A + (size_t)bm * K;
    const __half* Wb = W + (size_t)bn * K;

    float c[4][4][4];
#pragma unroll
    for (int mi = 0; mi < 4; mi++)
#pragma unroll
        for (int ni = 0; ni < 4; ni++)
#pragma unroll
            for (int e = 0; e < 4; e++) c[mi][ni][e] = 0.f;

    const int kt = K / 64;

    auto stage = [&](int buf, int k0) {
#pragma unroll
        for (int v = 0; v < 4; v++) {
            int linear = t + v * 256;
            int row = linear >> 3;
            int off = (linear & 7) * 8;
            __pipeline_memcpy_async(&AsBuf[buf][row * AST + off],
                                    Ab + (size_t)row * K + k0 + off, 16);
            __pipeline_memcpy_async(&BsBuf[buf][row * AST + off],
                                    Wb + (size_t)row * K + k0 + off, 16);
        }
        __pipeline_commit();
    };

    stage(0, 0);
    for (int it = 0; it < kt; it++) {
        __pipeline_wait_prior(0);
        __syncthreads();
        if (it + 1 < kt) stage((it + 1) & 1, (it + 1) * 64);

        const __half* Ap = AsBuf[it & 1];
        const __half* Bp = BsBuf[it & 1];
        uint32_t aBase = (uint32_t)__cvta_generic_to_shared(
            Ap + (wm * 64 + a_row) * AST + a_koff);
        uint32_t bBase = (uint32_t)__cvta_generic_to_shared(
            Bp + (wn * 32 + b_row) * AST + b_koff);

#pragma unroll
        for (int kk = 0; kk < 64; kk += 16) {
            uint32_t a[4][4];
#pragma unroll
            for (int mi = 0; mi < 4; mi++)
                ldsm4(a[mi][0], a[mi][1], a[mi][2], a[mi][3],
                      aBase + (uint32_t)((mi * 16 * AST + kk) * 2));
            uint32_t bf[8];
            ldsm4(bf[0], bf[1], bf[2], bf[3], bBase + (uint32_t)(kk * 2));
            ldsm4(bf[4], bf[5], bf[6], bf[7], bBase + (uint32_t)((16 * AST + kk) * 2));
#pragma unroll
            for (int mi = 0; mi < 4; mi++)
#pragma unroll
                for (int ni = 0; ni < 4; ni++)
                    mma_f16(c[mi][ni][0], c[mi][ni][1], c[mi][ni][2], c[mi][ni][3],
                            a[mi][0], a[mi][1], a[mi][2], a[mi][3],
                            bf[2 * ni], bf[2 * ni + 1]);
        }
    }

#pragma unroll
    for (int mi = 0; mi < 4; mi++) {
        int row0 = bm + wm * 64 + mi * 16 + quad;
#pragma unroll
        for (int ni = 0; ni < 4; ni++) {
            int col = bn + wn * 32 + ni * 8 + tig * 2;
            float2 bb = *(const float2*)&bias[col];
            float v00 = c[mi][ni][0] + bb.x, v01 = c[mi][ni][1] + bb.y;
            float v10 = c[mi][ni][2] + bb.x, v11 = c[mi][ni][3] + bb.y;
            if (RELU) {
                v00 = fmaxf(v00, 0.f); v01 = fmaxf(v01, 0.f);
                v10 = fmaxf(v10, 0.f); v11 = fmaxf(v11, 0.f);
            }
            if (HOUT) {
                __half* C = (__half*)Cv;
                *(__half2*)&C[(size_t)row0 * N + col]       = __floats2half2_rn(v00, v01);
                *(__half2*)&C[(size_t)(row0 + 8) * N + col] = __floats2half2_rn(v10, v11);
            } else {
                float* C = (float*)Cv;
                *(float2*)&C[(size_t)row0 * N + col]       = make_float2(v00, v01);
                *(float2*)&C[(size_t)(row0 + 8) * N + col] = make_float2(v10, v11);
            }
        }
    }
}

// ---------------- flash attention: fp16 mma, P in registers, exp2 softmax (R11) ----------------
#define KST 72
#define VST 72
#define KBUF (64 * KST)
#define VBUF (64 * VST)
#define ATTN_SMEM ((2 * KBUF + 2 * VBUF) * 2)   // 36864 B
#define QSCALE (0.125f * 1.44269504088896f)     // 1/sqrt(64) * log2(e)

__global__ __launch_bounds__(256, 2)
void attn_kernel(const __half* __restrict__ qkv, __half* __restrict__ out)
{
    extern __shared__ __half sma[];
    __half* Ksm[2] = { sma, sma + KBUF };
    __half* Vsm[2] = { sma + 2 * KBUF, sma + 2 * KBUF + VBUF };

    const int t    = threadIdx.x;
    const int lane = t & 31;
    const int w    = t >> 5;
    const int quad = lane >> 2;
    const int tig  = lane & 3;
    const int head = blockIdx.y;
    const int q0   = blockIdx.x * 128;
    const int coff = head * 64;

    const int b_row  = (lane & 7) + ((lane & 16) >> 1);
    const int b_koff = ((lane >> 3) & 1) * 8;
    const int v_row  = (lane & 7) + ((lane >> 3) & 1) * 8;
    const int v_coff = ((lane >> 4) & 1) * 8;

    auto stage = [&](int k0, int buf) {
#pragma unroll
        for (int v = 0; v < 2; v++) {
            int linear = t + v * 256;
            int row = linear >> 3;
            int off = (linear & 7) * 8;
            __pipeline_memcpy_async(&Ksm[buf][row * KST + off],
                                    &qkv[(size_t)(k0 + row) * H3 + H + coff + off], 16);
            __pipeline_memcpy_async(&Vsm[buf][row * VST + off],
                                    &qkv[(size_t)(k0 + row) * H3 + 2 * H + coff + off], 16);
        }
        __pipeline_commit();
    };

    uint32_t Qa[4][4];
    {
        const __half* qb = qkv + (size_t)(q0 + w * 16) * H3 + coff;
#pragma unroll
        for (int c = 0; c < 4; c++) {
#pragma unroll
            for (int e = 0; e < 4; e++) {
                int r   = quad + (e & 1) * 8;
                int col = c * 16 + (e >> 1) * 8 + tig * 2;
                float2 v = __half22float2(*(const __half2*)&qb[(size_t)r * H3 + col]);
                Qa[c][e] = pack_h2(v.x * QSCALE, v.y * QSCALE);
            }
        }
    }

    float o[8][4];
#pragma unroll
    for (int nb = 0; nb < 8; nb++)
#pragma unroll
        for (int e = 0; e < 4; e++) o[nb][e] = 0.f;
    float m0 = -1e30f, m1 = -1e30f, l0 = 0.f, l1 = 0.f;

    const int NITER = (SEQ + 63) / 64;   // 65

    stage(0, 0);
    for (int it = 0; it < NITER; it++) {
        const int k0 = it * 64;
        __pipeline_wait_prior(0);
        __syncthreads();
        if (it + 1 < NITER) stage((it + 1) * 64, (it + 1) & 1);

        const __half* Kb = Ksm[it & 1];
        const __half* Vb = Vsm[it & 1];

        uint32_t kBase = (uint32_t)__cvta_generic_to_shared(Kb + b_row * KST + b_koff);
        uint32_t vBase = (uint32_t)__cvta_generic_to_shared(Vb + v_row * VST + v_coff);

        // ---- S = Q @ K^T (scores in log2 domain via QSCALE) ----
        float s[8][4];
#pragma unroll
        for (int nb = 0; nb < 8; nb++)
            s[nb][0] = s[nb][1] = s[nb][2] = s[nb][3] = 0.f;
#pragma unroll
        for (int jn = 0; jn < 4; jn++) {
#pragma unroll
            for (int c = 0; c < 4; c++) {
                uint32_t bf[4];
                ldsm4(bf[0], bf[1], bf[2], bf[3],
                      kBase + (uint32_t)((jn * 16 * KST + c * 16) * 2));
                mma_f16(s[2*jn][0], s[2*jn][1], s[2*jn][2], s[2*jn][3],
                        Qa[c][0], Qa[c][1], Qa[c][2], Qa[c][3], bf[0], bf[1]);
                mma_f16(s[2*jn+1][0], s[2*jn+1][1], s[2*jn+1][2], s[2*jn+1][3],
                        Qa[c][0], Qa[c][1], Qa[c][2], Qa[c][3], bf[2], bf[3]);
            }
        }

        if (k0 + 64 > SEQ) {
#pragma unroll
            for (int jb = 0; jb < 8; jb++) {
                int col0 = k0 + jb * 8 + 2 * tig;
                if (col0 >= SEQ)     { s[jb][0] = -1e30f; s[jb][2] = -1e30f; }
                if (col0 + 1 >= SEQ) { s[jb][1] = -1e30f; s[jb][3] = -1e30f; }
            }
        }

        // ---- online softmax in log2 domain ----
        float mx0 = -1e30f, mx1 = -1e30f;
#pragma unroll
        for (int jb = 0; jb < 8; jb++) {
            mx0 = fmaxf(mx0, fmaxf(s[jb][0], s[jb][1]));
            mx1 = fmaxf(mx1, fmaxf(s[jb][2], s[jb][3]));
        }
        mx0 = fmaxf(mx0, __shfl_xor_sync(0xffffffffu, mx0, 1));
        mx0 = fmaxf(mx0, __shfl_xor_sync(0xffffffffu, mx0, 2));
        mx1 = fmaxf(mx1, __shfl_xor_sync(0xffffffffu, mx1, 1));
        mx1 = fmaxf(mx1, __shfl_xor_sync(0xffffffffu, mx1, 2));

        float mn0 = fmaxf(m0, mx0), mn1 = fmaxf(m1, mx1);
        float corr0 = ex2f(m0 - mn0), corr1 = ex2f(m1 - mn1);
        m0 = mn0; m1 = mn1;

        float sum0 = 0.f, sum1 = 0.f;
#pragma unroll
        for (int jb = 0; jb < 8; jb++) {
            float p0 = ex2f(s[jb][0] - mn0);
            float p1 = ex2f(s[jb][1] - mn0);
            float p2 = ex2f(s[jb][2] - mn1);
            float p3 = ex2f(s[jb][3] - mn1);
            sum0 += p0 + p1;
            sum1 += p2 + p3;
            s[jb][0] = p0; s[jb][1] = p1; s[jb][2] = p2; s[jb][3] = p3;
        }
        sum0 += __shfl_xor_sync(0xffffffffu, sum0, 1);
        sum0 += __shfl_xor_sync(0xffffffffu, sum0, 2);
        sum1 += __shfl_xor_sync(0xffffffffu, sum1, 1);
        sum1 += __shfl_xor_sync(0xffffffffu, sum1, 2);
        l0 = l0 * corr0 + sum0;
        l1 = l1 * corr1 + sum1;

#pragma unroll
        for (int nb = 0; nb < 8; nb++) {
            o[nb][0] *= corr0; o[nb][1] *= corr0;
            o[nb][2] *= corr1; o[nb][3] *= corr1;
        }

        // ---- O += P @ V (P packed straight from S accumulators) ----
#pragma unroll
        for (int kc = 0; kc < 4; kc++) {
            uint32_t pf0 = pack_h2(s[2*kc][0],   s[2*kc][1]);
            uint32_t pf1 = pack_h2(s[2*kc][2],   s[2*kc][3]);
            uint32_t pf2 = pack_h2(s[2*kc+1][0], s[2*kc+1][1]);
            uint32_t pf3 = pack_h2(s[2*kc+1][2], s[2*kc+1][3]);
#pragma unroll
            for (int jn = 0; jn < 4; jn++) {
                uint32_t bf[4];
                ldsm4t(bf[0], bf[1], bf[2], bf[3],
                       vBase + (uint32_t)((kc * 16 * VST + jn * 16) * 2));
                mma_f16(o[2*jn][0], o[2*jn][1], o[2*jn][2], o[2*jn][3],
                        pf0, pf1, pf2, pf3, bf[0], bf[1]);
                mma_f16(o[2*jn+1][0], o[2*jn+1][1], o[2*jn+1][2], o[2*jn+1][3],
                        pf0, pf1, pf2, pf3, bf[2], bf[3]);
            }
        }
    }

    float inv0 = 1.0f / l0, inv1 = 1.0f / l1;
    __half* ob0 = out + (size_t)(q0 + w * 16 + quad) * H + coff;
    __half* ob1 = out + (size_t)(q0 + w * 16 + quad + 8) * H + coff;
#pragma unroll
    for (int nb = 0; nb < 8; nb++) {
        *(__half2*)&ob0[nb * 8 + 2 * tig] = __floats2half2_rn(o[nb][0] * inv0, o[nb][1] * inv0);
        *(__half2*)&ob1[nb * 8 + 2 * tig] = __floats2half2_rn(o[nb][2] * inv1, o[nb][3] * inv1);
    }
}

// ---------------- fused add + LayerNorm (writes x and fp16 xh) ----------------
__global__ __launch_bounds__(256)
void addln_kernel(const float* __restrict__ a, const float* __restrict__ b,
                  const float* __restrict__ w, const float* __restrict__ wb,
                  float* __restrict__ outx, __half* __restrict__ outxh)
{
    int s = blockIdx.x;
    int t = threadIdx.x;
    const float4 av = ((const float4*)(a + (size_t)s * H))[t];
    const float4 bv = ((const float4*)(b + (size_t)s * H))[t];
    float v[4] = {av.x + bv.x, av.y + bv.y, av.z + bv.z, av.w + bv.w};

    float s1 = v[0] + v[1] + v[2] + v[3];
    float s2 = v[0]*v[0] + v[1]*v[1] + v[2]*v[2] + v[3]*v[3];
#pragma unroll
    for (int off = 16; off > 0; off >>= 1) {
        s1 += __shfl_xor_sync(0xffffffffu, s1, off);
        s2 += __shfl_xor_sync(0xffffffffu, s2, off);
    }
    __shared__ float r1[8], r2[8];
    int wid = t >> 5, lane = t & 31;
    if (lane == 0) { r1[wid] = s1; r2[wid] = s2; }
    __syncthreads();
    if (t == 0) {
        float a0 = 0.f, b0 = 0.f;
#pragma unroll
        for (int i = 0; i < 8; i++) { a0 += r1[i]; b0 += r2[i]; }
        r1[0] = a0; r2[0] = b0;
    }
    __syncthreads();
    float mean = r1[0] * (1.0f / H);
    float var  = r2[0] * (1.0f / H) - mean * mean;
    float rstd = rsqrtf(var + 1e-5f);

    const float4 wv  = ((const float4*)w)[t];
    const float4 wbv = ((const float4*)wb)[t];
    float4 ov;
    ov.x = (v[0] - mean) * rstd * wv.x + wbv.x;
    ov.y = (v[1] - mean) * rstd * wv.y + wbv.y;
    ov.z = (v[2] - mean) * rstd * wv.z + wbv.z;
    ov.w = (v[3] - mean) * rstd * wv.w + wbv.w;
    ((float4*)(outx + (size_t)s * H))[t] = ov;

    ((__half2*)(outxh + (size_t)s * H))[2 * t]     = __floats2half2_rn(ov.x, ov.y);
    ((__half2*)(outxh + (size_t)s * H))[2 * t + 1] = __floats2half2_rn(ov.z, ov.w);
}

// ---------------- final projection ----------------
__global__ void final_kernel(const float* __restrict__ x, const float* __restrict__ Wout,
                             const float* __restrict__ bout, float* __restrict__ out)
{
    int o = threadIdx.x;
    if (o >= OUTD) return;
    const float* w = Wout + (size_t)o * H;
    float acc = bout[o];
#pragma unroll 8
    for (int d = 0; d < H; d++) acc = fmaf(x[d], w[d], acc);
    out[o] = acc;
}

// ---------------- launch ----------------
extern "C" void kernel_launch(void* const* d_in, const int* in_sizes, int n_in,
                              void* d_out, int out_size)
{
    (void)in_sizes; (void)n_in; (void)out_size;
    const float* q     = (const float*)d_in[0];
    const float* p     = (const float*)d_in[1];
    const float* qm    = (const float*)d_in[2];
    const float* pm    = (const float*)d_in[3];
    const float* z     = (const float*)d_in[4];
    const float* Wq    = (const float*)d_in[5];
    const float* bq    = (const float*)d_in[6];
    const float* Wp    = (const float*)d_in[7];
    const float* bp    = (const float*)d_in[8];
    const float* Wz    = (const float*)d_in[9];
    const float* bz    = (const float*)d_in[10];
    const float* pos   = (const float*)d_in[11];
    const float* noise = (const float*)d_in[12];
    const float* Wqkv  = (const float*)d_in[13];
    const float* bqkv  = (const float*)d_in[14];
    const float* Wo    = (const float*)d_in[15];
    const float* bo    = (const float*)d_in[16];
    const float* ln1w  = (const float*)d_in[17];
    const float* ln1b  = (const float*)d_in[18];
    const float* W1    = (const float*)d_in[19];
    const float* b1    = (const float*)d_in[20];
    const float* W2    = (const float*)d_in[21];
    const float* b2    = (const float*)d_in[22];
    const float* ln2w  = (const float*)d_in[23];
    const float* ln2b  = (const float*)d_in[24];
    const float* Wout  = (const float*)d_in[25];
    const float* bout  = (const float*)d_in[26];

    float *x, *tmp;
    __half *xh, *qkvb, *attnb, *ff, *wqkv_h, *wo_h, *w1_h, *w2_h;
    cudaGetSymbolAddress((void**)&x,      g_x);
    cudaGetSymbolAddress((void**)&xh,     g_xh);
    cudaGetSymbolAddress((void**)&qkvb,   g_qkv);
    cudaGetSymbolAddress((void**)&attnb,  g_attn);
    cudaGetSymbolAddress((void**)&tmp,    g_tmp);
    cudaGetSymbolAddress((void**)&ff,     g_ff);
    cudaGetSymbolAddress((void**)&wqkv_h, g_wqkv_h);
    cudaGetSymbolAddress((void**)&wo_h,   g_wo_h);
    cudaGetSymbolAddress((void**)&w1_h,   g_w1_h);
    cudaGetSymbolAddress((void**)&w2_h,   g_w2_h);

    cudaFuncSetAttribute((const void*)tgemm<false,true>,  cudaFuncAttributeMaxDynamicSharedMemorySize, GEMM_SMEM);
    cudaFuncSetAttribute((const void*)tgemm<false,false>, cudaFuncAttributeMaxDynamicSharedMemorySize, GEMM_SMEM);
    cudaFuncSetAttribute((const void*)tgemm<true,true>,   cudaFuncAttributeMaxDynamicSharedMemorySize, GEMM_SMEM);
    cudaFuncSetAttribute((const void*)attn_kernel,        cudaFuncAttributeMaxDynamicSharedMemorySize, ATTN_SMEM);

    to_half_all_kernel<<<4096, 256>>>(Wqkv, wqkv_h, Wo, wo_h, W1, w1_h, W2, w2_h);

    embed_kernel<<<SEQP, 256>>>(q, p, qm, pm, z, Wq, bq, Wp, bp, Wz, bz, pos, noise, x, xh);

    const int MB = SEQP / 128;   // 33
    for (int i = 0; i < LAYERS; i++) {
        tgemm<false,true><<<dim3(H3 / 128, MB), 256, GEMM_SMEM>>>(
            xh, wqkv_h + (size_t)i * H3 * H, bqkv + (size_t)i * H3, qkvb, SEQP, H3, H);
        attn_kernel<<<dim3(SEQP / 128, NH), 256, ATTN_SMEM>>>(qkvb, attnb);
        tgemm<false,false><<<dim3(H / 128, MB), 256, GEMM_SMEM>>>(
            attnb, wo_h + (size_t)i * H * H, bo + (size_t)i * H, tmp, SEQP, H, H);
        addln_kernel<<<SEQP, 256>>>(x, tmp, ln1w + (size_t)i * H, ln1b + (size_t)i * H, x, xh);
        tgemm<true,true><<<dim3(FFD / 128, MB), 256, GEMM_SMEM>>>(
            xh, w1_h + (size_t)i * FFD * H, b1 + (size_t)i * FFD, ff, SEQP, FFD, H);
        tgemm<false,false><<<dim3(H / 128, MB), 256, GEMM_SMEM>>>(
            ff, w2_h + (size_t)i * H * FFD, b2 + (size_t)i * H, tmp, SEQP, H, FFD);
        addln_kernel<<<SEQP, 256>>>(x, tmp, ln2w + (size_t)i * H, ln2b + (size_t)i * H, x, xh);
    }

    final_kernel<<<1, 128>>>(x, Wout, bout, (float*)d_out);
}